// round 2
// baseline (speedup 1.0000x reference)
#include <cuda_runtime.h>
#include <math.h>

#define NTHREADS 128
#define TE_EDGE 32
#define TE_NODE 16
#define NMAX 50000
#define EMAX 600000

typedef unsigned long long u64;

// ---------------- device scratch (no allocations allowed) ----------------
__device__ float g_q[NMAX * 128];            // q = MLP_q(h)
__device__ float g_attn[NMAX * 128];         // segment-summed alpha*v
__device__ float g_mx[NMAX * 16];            // per-(node,head) running max
__device__ float g_den[NMAX * 16];           // per-(node,head) exp-sum
__device__ float g_scores[EMAX * 16];        // scores, then exp(scores-max) in place
__device__ float g_v[(long long)EMAX * 128]; // per-edge v (after e_w scaling)

// ---------------- packed f32x2 helpers (Blackwell FFMA2 — PTX only) ----------------
__device__ __forceinline__ u64 fma2(u64 a, u64 b, u64 c) {
    u64 d;
    asm("fma.rn.f32x2 %0, %1, %2, %3;" : "=l"(d) : "l"(a), "l"(b), "l"(c));
    return d;
}
__device__ __forceinline__ u64 pack2(float lo, float hi) {
    u64 r;
    asm("mov.b64 %0, {%1, %2};" : "=l"(r) : "f"(lo), "f"(hi));
    return r;
}
__device__ __forceinline__ float hsum2(u64 a) {
    float x, y;
    asm("mov.b64 {%0, %1}, %2;" : "=f"(x), "=f"(y) : "l"(a));
    return x + y;
}

// monotone float atomic max via signed/unsigned int tricks (init to -inf)
__device__ __forceinline__ void atomicMaxF(float* addr, float v) {
    if (v >= 0.f) atomicMax((int*)addr, __float_as_int(v));
    else          atomicMin((unsigned int*)addr, __float_as_uint(v));
}

// ---------------- tiled MLP via FFMA2: [TE, KIN] -> Linear -> LN -> ReLU -> Linear ----------------
// 128 threads; thread t owns output column t. in_s rows must be 16B-aligned (KIN % 4 == 0).
template <int KIN, int TE>
__device__ __forceinline__ void mlp_tile(
    const float* in_s, float* hid_s, float* mu_s, float* rs_s,
    const float* __restrict__ W1, const float* __restrict__ b1,
    const float* __restrict__ gam, const float* __restrict__ bet,
    const float* __restrict__ W2, const float* __restrict__ b2,
    float* out)
{
    const int t = threadIdx.x;
    u64 acc[TE];
    {
        const u64 z = pack2(b1[t], 0.f);
#pragma unroll
        for (int e = 0; e < TE; e++) acc[e] = z;
    }
    for (int i = 0; i < KIN; i += 4) {
        const u64 wp0 = pack2(W1[(i + 0) * 128 + t], W1[(i + 1) * 128 + t]);
        const u64 wp1 = pack2(W1[(i + 2) * 128 + t], W1[(i + 3) * 128 + t]);
#pragma unroll
        for (int e = 0; e < TE; e++) {
            const ulonglong2 x = *(const ulonglong2*)(in_s + e * KIN + i);
            acc[e] = fma2(x.x, wp0, acc[e]);
            acc[e] = fma2(x.y, wp1, acc[e]);
        }
    }
#pragma unroll
    for (int e = 0; e < TE; e++) hid_s[e * 128 + t] = hsum2(acc[e]);
    __syncthreads();

    // LayerNorm statistics: warp w handles rows w, w+4, ...
    const int w = t >> 5, lane = t & 31;
    for (int e = w; e < TE; e += 4) {
        float s = 0.f, s2 = 0.f;
#pragma unroll
        for (int j = 0; j < 4; j++) {
            const float v = hid_s[e * 128 + lane + j * 32];
            s += v; s2 += v * v;
        }
#pragma unroll
        for (int o = 16; o; o >>= 1) {
            s  += __shfl_down_sync(0xffffffffu, s, o);
            s2 += __shfl_down_sync(0xffffffffu, s2, o);
        }
        if (lane == 0) {
            const float mu = s * (1.f / 128.f);
            const float var = s2 * (1.f / 128.f) - mu * mu;
            mu_s[e] = mu;
            rs_s[e] = rsqrtf(var + 1e-5f);
        }
    }
    __syncthreads();

    // normalize + affine + ReLU in place
    const float gt = gam[t], bt = bet[t];
#pragma unroll
    for (int e = 0; e < TE; e++) {
        float v = hid_s[e * 128 + t];
        v = fmaf((v - mu_s[e]) * rs_s[e], gt, bt);
        hid_s[e * 128 + t] = fmaxf(v, 0.f);
    }
    __syncthreads();

    // second linear (KIN2 = 128)
    u64 acc2[TE];
    {
        const u64 z = pack2(b2[t], 0.f);
#pragma unroll
        for (int e = 0; e < TE; e++) acc2[e] = z;
    }
    for (int i = 0; i < 128; i += 4) {
        const u64 wp0 = pack2(W2[(i + 0) * 128 + t], W2[(i + 1) * 128 + t]);
        const u64 wp1 = pack2(W2[(i + 2) * 128 + t], W2[(i + 3) * 128 + t]);
#pragma unroll
        for (int e = 0; e < TE; e++) {
            const ulonglong2 x = *(const ulonglong2*)(hid_s + e * 128 + i);
            acc2[e] = fma2(x.x, wp0, acc2[e]);
            acc2[e] = fma2(x.y, wp1, acc2[e]);
        }
    }
#pragma unroll
    for (int e = 0; e < TE; e++) out[e] = hsum2(acc2[e]);
    __syncthreads(); // hid_s reusable by caller afterwards
}

// ---------------- kernels ----------------
__global__ void init_kernel(int n) {
    const int i = blockIdx.x * blockDim.x + threadIdx.x;
    if (i < n * 128) g_attn[i] = 0.f;
    if (i < n * 16) { g_mx[i] = __int_as_float(0xff800000); g_den[i] = 0.f; }
}

__global__ void __launch_bounds__(NTHREADS)
q_kernel(const float* __restrict__ h, int n,
         const float* W1, const float* b1, const float* gam,
         const float* bet, const float* W2, const float* b2) {
    __shared__ __align__(16) float in_s[TE_NODE * 128];
    __shared__ __align__(16) float hid_s[TE_NODE * 128];
    __shared__ float mu_s[TE_NODE], rs_s[TE_NODE];
    const int t = threadIdx.x;
    const int n0 = blockIdx.x * TE_NODE;
    const int ne = min(TE_NODE, n - n0);
    for (int e = 0; e < ne; e++) in_s[e * 128 + t] = h[(n0 + e) * 128 + t];
    __syncthreads();
    float out[TE_NODE];
    mlp_tile<128, TE_NODE>(in_s, hid_s, mu_s, rs_s, W1, b1, gam, bet, W2, b2, out);
    for (int e = 0; e < ne; e++) g_q[(n0 + e) * 128 + t] = out[e];
}

__global__ void __launch_bounds__(NTHREADS)
edge_kernel(const float* __restrict__ h,
            const float* __restrict__ rf,
            const float* __restrict__ ef,
            const float* __restrict__ ew,
            const int* __restrict__ srcI,
            const int* __restrict__ dstI, int Ecnt,
            const float* kW1, const float* kb1, const float* kg,
            const float* kbe, const float* kW2, const float* kb2,
            const float* vW1, const float* vb1, const float* vg,
            const float* vbe, const float* vW2, const float* vb2) {
    extern __shared__ __align__(16) float dsm[];
    float* in_s  = dsm;                            // TE_EDGE * 280
    float* hid_s = in_s + TE_EDGE * 280;           // TE_EDGE * 128
    float* mu_s  = hid_s + TE_EDGE * 128;          // TE_EDGE
    float* rs_s  = mu_s + TE_EDGE;                 // TE_EDGE
    float* ew_s  = rs_s + TE_EDGE;                 // TE_EDGE
    int*   dst_s = (int*)(ew_s + TE_EDGE);         // TE_EDGE

    const int t = threadIdx.x;
    const int e0 = blockIdx.x * TE_EDGE;
    const int ne = min(TE_EDGE, Ecnt - e0);

    for (int e = 0; e < ne; e++) {
        const int idx = e0 + e;
        const int dd = dstI[idx], ss = srcI[idx];
        if (t == 0) { dst_s[e] = dd; ew_s[e] = ew[idx]; }
        // kv_input = [edge_feat(4), r_feat(20), h[dst](128), h[src](128)]
        for (int i = t; i < 280; i += NTHREADS) {
            float val;
            if (i < 4)        val = ef[idx * 4 + i];
            else if (i < 24)  val = rf[idx * 20 + (i - 4)];
            else if (i < 152) val = h[dd * 128 + (i - 24)];
            else              val = h[ss * 128 + (i - 152)];
            in_s[e * 280 + i] = val;
        }
    }
    __syncthreads();

    // K MLP + per-head attention scores
    float kout[TE_EDGE];
    mlp_tile<280, TE_EDGE>(in_s, hid_s, mu_s, rs_s, kW1, kb1, kg, kbe, kW2, kb2, kout);
    for (int e = 0; e < ne; e++) {
        float val = kout[e] * g_q[dst_s[e] * 128 + t];
        val += __shfl_down_sync(0xffffffffu, val, 4, 8);
        val += __shfl_down_sync(0xffffffffu, val, 2, 8);
        val += __shfl_down_sync(0xffffffffu, val, 1, 8);
        if ((t & 7) == 0) {
            const float sc = val * 0.35355339059327373f; // 1/sqrt(8)
            g_scores[(e0 + e) * 16 + (t >> 3)] = sc;
            atomicMaxF(&g_mx[dst_s[e] * 16 + (t >> 3)], sc);
        }
    }

    // V MLP (scaled by e_w)
    float vout[TE_EDGE];
    mlp_tile<280, TE_EDGE>(in_s, hid_s, mu_s, rs_s, vW1, vb1, vg, vbe, vW2, vb2, vout);
    for (int e = 0; e < ne; e++)
        g_v[(long long)(e0 + e) * 128 + t] = vout[e] * ew_s[e];
}

__global__ void softmax_kernel(const int* __restrict__ dstI, int Ecnt) {
    const int gid = blockIdx.x * blockDim.x + threadIdx.x;
    if (gid >= Ecnt * 16) return;
    const int e = gid >> 4, hh = gid & 15;
    const int node = dstI[e];
    const float exv = expf(g_scores[gid] - g_mx[node * 16 + hh]);
    g_scores[gid] = exv;
    atomicAdd(&g_den[node * 16 + hh], exv);
}

__global__ void aggregate_kernel(const int* __restrict__ dstI, int Ecnt) {
    const int gid = blockIdx.x * blockDim.x + threadIdx.x;
    if (gid >= Ecnt * 128) return;
    const int e = gid >> 7, t = gid & 127;
    const int node = dstI[e];
    const int hh = t >> 3;
    const float alpha = g_scores[e * 16 + hh] / g_den[node * 16 + hh];
    atomicAdd(&g_attn[node * 128 + t], alpha * g_v[gid]);
}

__global__ void __launch_bounds__(NTHREADS)
out_kernel(const float* __restrict__ h, float* __restrict__ outp, int n,
           const float* W1, const float* b1, const float* gam,
           const float* bet, const float* W2, const float* b2) {
    __shared__ __align__(16) float in_s[TE_NODE * 256];
    __shared__ __align__(16) float hid_s[TE_NODE * 128];
    __shared__ float mu_s[TE_NODE], rs_s[TE_NODE];
    const int t = threadIdx.x;
    const int n0 = blockIdx.x * TE_NODE;
    const int ne = min(TE_NODE, n - n0);
    for (int e = 0; e < ne; e++) {
        const int node = n0 + e;
        for (int i = t; i < 256; i += NTHREADS)
            in_s[e * 256 + i] = (i < 128) ? g_attn[node * 128 + i]
                                          : h[node * 128 + (i - 128)];
    }
    __syncthreads();
    float out[TE_NODE];
    mlp_tile<256, TE_NODE>(in_s, hid_s, mu_s, rs_s, W1, b1, gam, bet, W2, b2, out);
    for (int e = 0; e < ne; e++) outp[(n0 + e) * 128 + t] = out[e];
}

// ---------------- launch ----------------
extern "C" void kernel_launch(void* const* d_in, const int* in_sizes, int n_in,
                              void* d_out, int out_size) {
    // Discover inputs by element count (robust to metadata ordering).
    int ih = -1, ir = -1, ief = -1, iei = -1, iew = -1, xk0 = -1;
    for (int i = 0; i < n_in; i++) {
        switch (in_sizes[i]) {
            case 6400000:  if (ih  < 0) ih  = i; break; // h [N,128]
            case 12000000: if (ir  < 0) ir  = i; break; // r_feat [E,20]
            case 2400000:  if (ief < 0) ief = i; break; // edge_feat [E,4]
            case 1200000:  if (iei < 0) iei = i; break; // edge_index [2,E]
            case 600000:   if (iew < 0) iew = i; break; // e_w [E]
            case 35840:    if (xk0 < 0) xk0 = i; break; // xk_W1 [280,128] (first)
            default: break;
        }
    }
    // MLP groups are contiguous in order xk, xv, xq, out; each = W1,b1,g,beta,W2,b2
    const int xv0 = xk0 + 6, xq0 = xk0 + 12, o0 = xk0 + 18;

    const float* h   = (const float*)d_in[ih];
    const float* rf  = (const float*)d_in[ir];
    const float* ef  = (const float*)d_in[ief];
    const float* ew  = (const float*)d_in[iew];
    const int*   ei  = (const int*)d_in[iei];
    const int N = in_sizes[ih] / 128;
    const int E = in_sizes[iew];
    const int* srcI = ei;
    const int* dstI = ei + E;

#define G(base, off) ((const float*)d_in[(base) + (off)])

    float* outp = (float*)d_out;

    // Dynamic smem for the edge kernel (52.7 KB > 48 KB static limit)
    const int smem_edge = (TE_EDGE * 280 + TE_EDGE * 128 + TE_EDGE * 4) * 4;
    static int attr_done = 0;
    if (!attr_done) {
        cudaFuncSetAttribute(edge_kernel,
                             cudaFuncAttributeMaxDynamicSharedMemorySize, smem_edge);
        attr_done = 1;
    }

    // 1. init scratch
    {
        const int n_el = N * 128;
        init_kernel<<<(n_el + 255) / 256, 256>>>(N);
    }
    // 2. q = MLP_q(h)
    q_kernel<<<(N + TE_NODE - 1) / TE_NODE, NTHREADS>>>(
        h, N, G(xq0,0), G(xq0,1), G(xq0,2), G(xq0,3), G(xq0,4), G(xq0,5));
    // 3. per-edge k/v MLPs + scores + running max
    edge_kernel<<<(E + TE_EDGE - 1) / TE_EDGE, NTHREADS, smem_edge>>>(
        h, rf, ef, ew, srcI, dstI, E,
        G(xk0,0), G(xk0,1), G(xk0,2), G(xk0,3), G(xk0,4), G(xk0,5),
        G(xv0,0), G(xv0,1), G(xv0,2), G(xv0,3), G(xv0,4), G(xv0,5));
    // 4. exp + denominator
    softmax_kernel<<<(E * 16 + 255) / 256, 256>>>(dstI, E);
    // 5. alpha * v scatter-add
    {
        const long long tot = (long long)E * 128;
        aggregate_kernel<<<(int)((tot + 255) / 256), 256>>>(dstI, E);
    }
    // 6. output MLP on concat(attn, h)
    out_kernel<<<(N + TE_NODE - 1) / TE_NODE, NTHREADS>>>(
        h, outp, N, G(o0,0), G(o0,1), G(o0,2), G(o0,3), G(o0,4), G(o0,5));
#undef G
}

// round 4
// speedup vs baseline: 2.2900x; 2.2900x over previous
#include <cuda_runtime.h>
#include <math.h>

#define TILE 16
#define NTHREADS 128
#define NMAX 50000
#define EMAX 600000

// ---------------- device scratch (no allocations allowed) ----------------
__device__ float g_q[NMAX * 128];      // q = MLP_q(h)
__device__ float g_kHd[NMAX * 128];    // h @ kW1[24:152]
__device__ float g_kHs[NMAX * 128];    // h @ kW1[152:280]
__device__ float g_vHd[NMAX * 128];    // h @ vW1[24:152]
__device__ float g_vHs[NMAX * 128];    // h @ vW1[152:280]
__device__ float g_attn[NMAX * 128];   // segment-summed alpha*v
__device__ float g_mx[NMAX * 16];      // per-(node,head) running max
__device__ float g_den[NMAX * 16];     // per-(node,head) exp-sum
__device__ float g_scores[EMAX * 16];  // scores, then exp(scores-max) in place

// monotone float atomic max via signed/unsigned int tricks (init to -inf)
__device__ __forceinline__ void atomicMaxF(float* addr, float v) {
    if (v >= 0.f) atomicMax((int*)addr, __float_as_int(v));
    else          atomicMin((unsigned int*)addr, __float_as_uint(v));
}

// ---------------- LN(+affine)+ReLU over hid_s rows ----------------
template <int TE>
__device__ __forceinline__ void ln_relu(float* hid_s, float* mu_s, float* rs_s,
                                        const float* __restrict__ gam,
                                        const float* __restrict__ bet) {
    const int t = threadIdx.x;
    const int w = t >> 5, lane = t & 31;
    __syncthreads();
    for (int e = w; e < TE; e += 4) {
        float s = 0.f, s2 = 0.f;
#pragma unroll
        for (int j = 0; j < 4; j++) {
            const float v = hid_s[e * 128 + lane + j * 32];
            s += v; s2 += v * v;
        }
#pragma unroll
        for (int o = 16; o; o >>= 1) {
            s  += __shfl_down_sync(0xffffffffu, s, o);
            s2 += __shfl_down_sync(0xffffffffu, s2, o);
        }
        if (lane == 0) {
            const float mu = s * (1.f / 128.f);
            const float var = s2 * (1.f / 128.f) - mu * mu;
            mu_s[e] = mu;
            rs_s[e] = rsqrtf(var + 1e-5f);
        }
    }
    __syncthreads();
    const float gt = gam[t], bt = bet[t];
#pragma unroll
    for (int e = 0; e < TE; e++) {
        float v = hid_s[e * 128 + t];
        v = fmaf((v - mu_s[e]) * rs_s[e], gt, bt);
        hid_s[e * 128 + t] = fmaxf(v, 0.f);
    }
    __syncthreads();
}

// second linear 128 -> 128, thread t owns column t
template <int TE>
__device__ __forceinline__ void lin2(const float* hid_s,
                                     const float* __restrict__ W2,
                                     const float* __restrict__ b2, float* out) {
    const int t = threadIdx.x;
    const float bb = b2[t];
#pragma unroll
    for (int e = 0; e < TE; e++) out[e] = bb;
    for (int i = 0; i < 128; i += 4) {
        const float w0 = W2[(i + 0) * 128 + t];
        const float w1 = W2[(i + 1) * 128 + t];
        const float w2 = W2[(i + 2) * 128 + t];
        const float w3 = W2[(i + 3) * 128 + t];
#pragma unroll
        for (int e = 0; e < TE; e++) {
            const float4 x = *(const float4*)(hid_s + e * 128 + i);
            out[e] = fmaf(x.x, w0, out[e]);
            out[e] = fmaf(x.y, w1, out[e]);
            out[e] = fmaf(x.z, w2, out[e]);
            out[e] = fmaf(x.w, w3, out[e]);
        }
    }
}

// full MLP for node kernels (first linear from shared input)
template <int KIN, int TE>
__device__ __forceinline__ void mlp_tile(
    const float* in_s, float* hid_s, float* mu_s, float* rs_s,
    const float* __restrict__ W1, const float* __restrict__ b1,
    const float* __restrict__ gam, const float* __restrict__ bet,
    const float* __restrict__ W2, const float* __restrict__ b2, float* out) {
    const int t = threadIdx.x;
    float acc[TE];
    const float bb1 = b1[t];
#pragma unroll
    for (int e = 0; e < TE; e++) acc[e] = bb1;
    for (int i = 0; i < KIN; i += 4) {
        const float w0 = W1[(i + 0) * 128 + t];
        const float w1 = W1[(i + 1) * 128 + t];
        const float w2 = W1[(i + 2) * 128 + t];
        const float w3 = W1[(i + 3) * 128 + t];
#pragma unroll
        for (int e = 0; e < TE; e++) {
            const float4 x = *(const float4*)(in_s + e * KIN + i);
            acc[e] = fmaf(x.x, w0, acc[e]);
            acc[e] = fmaf(x.y, w1, acc[e]);
            acc[e] = fmaf(x.z, w2, acc[e]);
            acc[e] = fmaf(x.w, w3, acc[e]);
        }
    }
#pragma unroll
    for (int e = 0; e < TE; e++) hid_s[e * 128 + t] = acc[e];
    ln_relu<TE>(hid_s, mu_s, rs_s, gam, bet);
    lin2<TE>(hid_s, W2, b2, out);
    __syncthreads();
}

// 128->128 projection (no bias): acc[e] = in_s[e]@W
template <int TE>
__device__ __forceinline__ void proj_tile(const float* in_s,
                                          const float* __restrict__ W,
                                          float* acc) {
    const int t = threadIdx.x;
#pragma unroll
    for (int e = 0; e < TE; e++) acc[e] = 0.f;
    for (int i = 0; i < 128; i += 4) {
        const float w0 = W[(i + 0) * 128 + t];
        const float w1 = W[(i + 1) * 128 + t];
        const float w2 = W[(i + 2) * 128 + t];
        const float w3 = W[(i + 3) * 128 + t];
#pragma unroll
        for (int e = 0; e < TE; e++) {
            const float4 x = *(const float4*)(in_s + e * 128 + i);
            acc[e] = fmaf(x.x, w0, acc[e]);
            acc[e] = fmaf(x.y, w1, acc[e]);
            acc[e] = fmaf(x.z, w2, acc[e]);
            acc[e] = fmaf(x.w, w3, acc[e]);
        }
    }
}

// ---------------- kernels ----------------
__global__ void init_kernel(int n) {
    const int i = blockIdx.x * blockDim.x + threadIdx.x;
    if (i < n * 128) g_attn[i] = 0.f;
    if (i < n * 16) { g_mx[i] = __int_as_float(0xff800000); g_den[i] = 0.f; }
}

// node prep: q MLP + 4 projections (kHd,kHs,vHd,vHs)
__global__ void __launch_bounds__(NTHREADS)
nodeprep_kernel(const float* __restrict__ h, int n,
                const float* qW1, const float* qb1, const float* qg,
                const float* qbe, const float* qW2, const float* qb2,
                const float* kW1, const float* vW1) {
    __shared__ __align__(16) float in_s[TILE * 128];
    __shared__ __align__(16) float hid_s[TILE * 128];
    __shared__ float mu_s[TILE], rs_s[TILE];
    const int t = threadIdx.x;
    const int n0 = blockIdx.x * TILE;
    const int ne = min(TILE, n - n0);
    for (int e = 0; e < ne; e++) in_s[e * 128 + t] = h[(n0 + e) * 128 + t];
    __syncthreads();

    float out[TILE];
    mlp_tile<128, TILE>(in_s, hid_s, mu_s, rs_s, qW1, qb1, qg, qbe, qW2, qb2, out);
    for (int e = 0; e < ne; e++) g_q[(n0 + e) * 128 + t] = out[e];

    proj_tile<TILE>(in_s, kW1 + 24 * 128, out);
    for (int e = 0; e < ne; e++) g_kHd[(n0 + e) * 128 + t] = out[e];
    proj_tile<TILE>(in_s, kW1 + 152 * 128, out);
    for (int e = 0; e < ne; e++) g_kHs[(n0 + e) * 128 + t] = out[e];
    proj_tile<TILE>(in_s, vW1 + 24 * 128, out);
    for (int e = 0; e < ne; e++) g_vHd[(n0 + e) * 128 + t] = out[e];
    proj_tile<TILE>(in_s, vW1 + 152 * 128, out);
    for (int e = 0; e < ne; e++) g_vHs[(n0 + e) * 128 + t] = out[e];
}

// edge pass A: k-MLP via gather-add + small GEMM, scores + atomicMax
__global__ void __launch_bounds__(NTHREADS)
edgeA_kernel(const float* __restrict__ rf, const float* __restrict__ ef,
             const int* __restrict__ srcI, const int* __restrict__ dstI, int Ecnt,
             const float* kW1, const float* kb1, const float* kg,
             const float* kbe, const float* kW2, const float* kb2) {
    __shared__ __align__(16) float sm_in[TILE * 24];
    __shared__ __align__(16) float hid_s[TILE * 128];
    __shared__ float mu_s[TILE], rs_s[TILE];
    __shared__ int dst_s[TILE], src_s[TILE];
    const int t = threadIdx.x;
    const int e0 = blockIdx.x * TILE;
    const int ne = min(TILE, Ecnt - e0);

    if (t < ne) { dst_s[t] = dstI[e0 + t]; src_s[t] = srcI[e0 + t]; }
    for (int j = t; j < ne * 24; j += NTHREADS) {
        const int e = j / 24, i = j % 24;
        sm_in[e * 24 + i] = (i < 4) ? ef[(e0 + e) * 4 + i] : rf[(e0 + e) * 20 + (i - 4)];
    }
    __syncthreads();

    // first layer: bias + gathered node projections + small GEMM over 24 dims
    float acc[TILE];
    const float bb1 = kb1[t];
#pragma unroll
    for (int e = 0; e < TILE; e++) {
        if (e < ne)
            acc[e] = bb1 + g_kHd[dst_s[e] * 128 + t] + g_kHs[src_s[e] * 128 + t];
        else acc[e] = 0.f;
    }
    for (int i = 0; i < 24; i += 4) {
        const float w0 = kW1[(i + 0) * 128 + t];
        const float w1 = kW1[(i + 1) * 128 + t];
        const float w2 = kW1[(i + 2) * 128 + t];
        const float w3 = kW1[(i + 3) * 128 + t];
#pragma unroll
        for (int e = 0; e < TILE; e++) {
            const float4 x = *(const float4*)(sm_in + e * 24 + i);
            acc[e] = fmaf(x.x, w0, acc[e]);
            acc[e] = fmaf(x.y, w1, acc[e]);
            acc[e] = fmaf(x.z, w2, acc[e]);
            acc[e] = fmaf(x.w, w3, acc[e]);
        }
    }
#pragma unroll
    for (int e = 0; e < TILE; e++) hid_s[e * 128 + t] = acc[e];
    ln_relu<TILE>(hid_s, mu_s, rs_s, kg, kbe);
    float kout[TILE];
    lin2<TILE>(hid_s, kW2, kb2, kout);

    // per-head scores vs q[dst]
    for (int e = 0; e < ne; e++) {
        float val = kout[e] * g_q[dst_s[e] * 128 + t];
        val += __shfl_down_sync(0xffffffffu, val, 4, 8);
        val += __shfl_down_sync(0xffffffffu, val, 2, 8);
        val += __shfl_down_sync(0xffffffffu, val, 1, 8);
        if ((t & 7) == 0) {
            const float sc = val * 0.35355339059327373f; // 1/sqrt(8)
            g_scores[(e0 + e) * 16 + (t >> 3)] = sc;
            atomicMaxF(&g_mx[dst_s[e] * 16 + (t >> 3)], sc);
        }
    }
}

__global__ void softmax_kernel(const int* __restrict__ dstI, int Ecnt) {
    const int gid = blockIdx.x * blockDim.x + threadIdx.x;
    if (gid >= Ecnt * 16) return;
    const int e = gid >> 4, hh = gid & 15;
    const int node = dstI[e];
    const float exv = expf(g_scores[gid] - g_mx[node * 16 + hh]);
    g_scores[gid] = exv;
    atomicAdd(&g_den[node * 16 + hh], exv);
}

// edge pass B: v-MLP via gather-add + fused alpha*v scatter
__global__ void __launch_bounds__(NTHREADS)
edgeB_kernel(const float* __restrict__ rf, const float* __restrict__ ef,
             const float* __restrict__ ew,
             const int* __restrict__ srcI, const int* __restrict__ dstI, int Ecnt,
             const float* vW1, const float* vb1, const float* vg,
             const float* vbe, const float* vW2, const float* vb2) {
    __shared__ __align__(16) float sm_in[TILE * 24];
    __shared__ __align__(16) float hid_s[TILE * 128];
    __shared__ float mu_s[TILE], rs_s[TILE], ew_s[TILE];
    __shared__ int dst_s[TILE], src_s[TILE];
    const int t = threadIdx.x;
    const int e0 = blockIdx.x * TILE;
    const int ne = min(TILE, Ecnt - e0);

    if (t < ne) {
        dst_s[t] = dstI[e0 + t];
        src_s[t] = srcI[e0 + t];
        ew_s[t] = ew[e0 + t];
    }
    for (int j = t; j < ne * 24; j += NTHREADS) {
        const int e = j / 24, i = j % 24;
        sm_in[e * 24 + i] = (i < 4) ? ef[(e0 + e) * 4 + i] : rf[(e0 + e) * 20 + (i - 4)];
    }
    __syncthreads();

    float acc[TILE];
    const float bb1 = vb1[t];
#pragma unroll
    for (int e = 0; e < TILE; e++) {
        if (e < ne)
            acc[e] = bb1 + g_vHd[dst_s[e] * 128 + t] + g_vHs[src_s[e] * 128 + t];
        else acc[e] = 0.f;
    }
    for (int i = 0; i < 24; i += 4) {
        const float w0 = vW1[(i + 0) * 128 + t];
        const float w1 = vW1[(i + 1) * 128 + t];
        const float w2 = vW1[(i + 2) * 128 + t];
        const float w3 = vW1[(i + 3) * 128 + t];
#pragma unroll
        for (int e = 0; e < TILE; e++) {
            const float4 x = *(const float4*)(sm_in + e * 24 + i);
            acc[e] = fmaf(x.x, w0, acc[e]);
            acc[e] = fmaf(x.y, w1, acc[e]);
            acc[e] = fmaf(x.z, w2, acc[e]);
            acc[e] = fmaf(x.w, w3, acc[e]);
        }
    }
#pragma unroll
    for (int e = 0; e < TILE; e++) hid_s[e * 128 + t] = acc[e];
    ln_relu<TILE>(hid_s, mu_s, rs_s, vg, vbe);
    float vout[TILE];
    lin2<TILE>(hid_s, vW2, vb2, vout);

    // alpha * v * e_w, scattered to destination node
    const int hh = t >> 3;
    for (int e = 0; e < ne; e++) {
        const int dd = dst_s[e];
        const float alpha = g_scores[(e0 + e) * 16 + hh] / g_den[dd * 16 + hh];
        atomicAdd(&g_attn[dd * 128 + t], vout[e] * ew_s[e] * alpha);
    }
}

__global__ void __launch_bounds__(NTHREADS)
out_kernel(const float* __restrict__ h, float* __restrict__ outp, int n,
           const float* W1, const float* b1, const float* gam,
           const float* bet, const float* W2, const float* b2) {
    __shared__ __align__(16) float in_s[TILE * 256];
    __shared__ __align__(16) float hid_s[TILE * 128];
    __shared__ float mu_s[TILE], rs_s[TILE];
    const int t = threadIdx.x;
    const int n0 = blockIdx.x * TILE;
    const int ne = min(TILE, n - n0);
    for (int e = 0; e < ne; e++) {
        const int node = n0 + e;
        in_s[e * 256 + t] = g_attn[node * 128 + t];
        in_s[e * 256 + 128 + t] = h[node * 128 + t];
    }
    __syncthreads();
    float out[TILE];
    mlp_tile<256, TILE>(in_s, hid_s, mu_s, rs_s, W1, b1, gam, bet, W2, b2, out);
    for (int e = 0; e < ne; e++) outp[(n0 + e) * 128 + t] = out[e];
}

// ---------------- launch ----------------
extern "C" void kernel_launch(void* const* d_in, const int* in_sizes, int n_in,
                              void* d_out, int out_size) {
    int ih = -1, ir = -1, ief = -1, iei = -1, iew = -1, xk0 = -1;
    for (int i = 0; i < n_in; i++) {
        switch (in_sizes[i]) {
            case 6400000:  if (ih  < 0) ih  = i; break; // h [N,128]
            case 12000000: if (ir  < 0) ir  = i; break; // r_feat [E,20]
            case 2400000:  if (ief < 0) ief = i; break; // edge_feat [E,4]
            case 1200000:  if (iei < 0) iei = i; break; // edge_index [2,E]
            case 600000:   if (iew < 0) iew = i; break; // e_w [E]
            case 35840:    if (xk0 < 0) xk0 = i; break; // xk_W1 [280,128] (first)
            default: break;
        }
    }
    const int xv0 = xk0 + 6, xq0 = xk0 + 12, o0 = xk0 + 18;

    const float* h   = (const float*)d_in[ih];
    const float* rf  = (const float*)d_in[ir];
    const float* ef  = (const float*)d_in[ief];
    const float* ew  = (const float*)d_in[iew];
    const int*   ei  = (const int*)d_in[iei];
    const int N = in_sizes[ih] / 128;
    const int E = in_sizes[iew];
    const int* srcI = ei;
    const int* dstI = ei + E;

#define G(base, off) ((const float*)d_in[(base) + (off)])
    float* outp = (float*)d_out;

    // 1. init scratch
    init_kernel<<<(N * 128 + 255) / 256, 256>>>(N);
    // 2. node prep: q MLP + 4 projections
    nodeprep_kernel<<<(N + TILE - 1) / TILE, NTHREADS>>>(
        h, N, G(xq0,0), G(xq0,1), G(xq0,2), G(xq0,3), G(xq0,4), G(xq0,5),
        G(xk0,0), G(xv0,0));
    // 3. edge pass A: k MLP + scores + max
    edgeA_kernel<<<(E + TILE - 1) / TILE, NTHREADS>>>(
        rf, ef, srcI, dstI, E,
        G(xk0,0), G(xk0,1), G(xk0,2), G(xk0,3), G(xk0,4), G(xk0,5));
    // 4. exp + denominator
    softmax_kernel<<<(E * 16 + 255) / 256, 256>>>(dstI, E);
    // 5. edge pass B: v MLP + fused alpha*v scatter
    edgeB_kernel<<<(E + TILE - 1) / TILE, NTHREADS>>>(
        rf, ef, ew, srcI, dstI, E,
        G(xv0,0), G(xv0,1), G(xv0,2), G(xv0,3), G(xv0,4), G(xv0,5));
    // 6. output MLP on concat(attn, h)
    out_kernel<<<(N + TILE - 1) / TILE, NTHREADS>>>(
        h, outp, N, G(o0,0), G(o0,1), G(o0,2), G(o0,3), G(o0,4), G(o0,5));
#undef G
}